// round 4
// baseline (speedup 1.0000x reference)
#include <cuda_runtime.h>
#include <cstdint>

#define Bn   16
#define ND   8192
#define NE   16384
#define NEDGE 65536
#define H    128
#define XDS  129   // padded row stride (u64) for duplicated X tile

typedef unsigned long long u64;

// ---------------- scratch ----------------
__device__ float g_Y[(size_t)Bn * ND * H];       // hD @ W_d2e^T
__device__ float g_aggPre[(size_t)Bn * ND * H];  // mean gather hE_new
__device__ float g_Wt[4 * H * H];                // transposed weights [k][c]

__device__ int g_cntE[NE];
__device__ int g_offE[NE + 1];
__device__ int g_curE[NE];
__device__ int g_lstE[NEDGE];

__device__ int g_cntD[ND];
__device__ int g_offD[ND + 1];
__device__ int g_curD[ND];
__device__ int g_lstD[NEDGE];

// ---------------- setup kernels ----------------
__global__ void k_wt4(const float* __restrict__ W0, const float* __restrict__ W1,
                      const float* __restrict__ W2, const float* __restrict__ W3,
                      float* __restrict__ Wt) {
    int g = blockIdx.x * 256 + threadIdx.x;        // 0..65535
    int m = g >> 14;
    int idx = g & 16383;
    int k = idx >> 7, c = idx & 127;
    const float* W = (m == 0) ? W0 : (m == 1) ? W1 : (m == 2) ? W2 : W3;
    Wt[g] = W[c * H + k];
}

__global__ void k_zero() {
    int i = blockIdx.x * 256 + threadIdx.x;
    if (i < NE) g_cntE[i] = 0;
    if (i < ND) g_cntD[i] = 0;
}

__global__ void k_count(const int* __restrict__ e_d2e, const int* __restrict__ e_e2d) {
    int e = blockIdx.x * blockDim.x + threadIdx.x;
    if (e >= NEDGE) return;
    atomicAdd(&g_cntE[e_d2e[NEDGE + e]], 1);
    atomicAdd(&g_cntD[e_e2d[NEDGE + e]], 1);
}

__global__ void k_scan2() {
    const int* cnt = blockIdx.x ? g_cntD : g_cntE;
    int* off       = blockIdx.x ? g_offD : g_offE;
    int* cur       = blockIdx.x ? g_curD : g_curE;
    int n          = blockIdx.x ? ND : NE;
    __shared__ int sm[1024];
    __shared__ int s_run;
    int tid = threadIdx.x;
    if (tid == 0) s_run = 0;
    __syncthreads();
    for (int base = 0; base < n; base += 1024) {
        int v = (base + tid < n) ? cnt[base + tid] : 0;
        sm[tid] = v;
        __syncthreads();
        for (int d = 1; d < 1024; d <<= 1) {
            int t = (tid >= d) ? sm[tid - d] : 0;
            __syncthreads();
            sm[tid] += t;
            __syncthreads();
        }
        int incl = sm[tid];
        int run = s_run;
        if (base + tid < n) {
            off[base + tid] = run + incl - v;
            cur[base + tid] = run + incl - v;
        }
        __syncthreads();
        if (tid == 1023) s_run = run + incl;
        __syncthreads();
    }
    if (tid == 0) off[n] = s_run;
}

__global__ void k_fill(const int* __restrict__ e_d2e, const int* __restrict__ e_e2d) {
    int e = blockIdx.x * blockDim.x + threadIdx.x;
    if (e >= NEDGE) return;
    {
        int d = e_d2e[NEDGE + e];
        int p = atomicAdd(&g_curE[d], 1);
        g_lstE[p] = e_d2e[e];
    }
    {
        int d = e_e2d[NEDGE + e];
        int p = atomicAdd(&g_curD[d], 1);
        g_lstD[p] = e_e2d[e];
    }
}

// ---------------- mean-gather: warp per (node, batch) ----------------
__global__ void k_agg(const float* __restrict__ SRC, const int* __restrict__ off,
                      const int* __restrict__ lst, float* __restrict__ agg,
                      int nNodes, long srcStride) {
    int gw = (blockIdx.x * blockDim.x + threadIdx.x) >> 5;
    if (gw >= nNodes * Bn) return;
    int node = gw % nNodes;
    int b    = gw / nNodes;
    int lane = threadIdx.x & 31;

    int s = off[node], e = off[node + 1];
    float4 a = make_float4(0.f, 0.f, 0.f, 0.f);
    const float* base = SRC + (size_t)b * srcStride;
    for (int j = s; j < e; ++j) {
        int src = lst[j];
        float4 v = reinterpret_cast<const float4*>(base + (size_t)src * H)[lane];
        a.x += v.x; a.y += v.y; a.z += v.z; a.w += v.w;
    }
    float sc = 1.0f / fmaxf((float)(e - s), 1.0f);
    a.x *= sc; a.y *= sc; a.z *= sc; a.w *= sc;
    reinterpret_cast<float4*>(agg + ((size_t)b * nNodes + node) * H)[lane] = a;
}

// ---------------- GEMM building blocks ----------------
// load 128x128 float tile into duplicated-u64 smem tile (row stride XDS)
__device__ __forceinline__ void tile_load_dup(const float* __restrict__ g,
                                              u64* __restrict__ s, int t) {
#pragma unroll
    for (int i = 0; i < 64; i++) {
        int idx = t + 256 * i;
        float v = __ldg(g + idx);
        u64 d;
        asm("mov.b64 %0, {%1, %1};" : "=l"(d) : "f"(v));
        s[(idx >> 7) * XDS + (idx & 127)] = d;
    }
}

__device__ __forceinline__ void tile_load(const float* __restrict__ g,
                                          float* __restrict__ s, int t) {
    const float4* g4 = reinterpret_cast<const float4*>(g);
    float4* s4 = reinterpret_cast<float4*>(s);
#pragma unroll
    for (int i = 0; i < 16; i++) s4[t + 256 * i] = g4[t + 256 * i];
}

// pure f32x2 inner loop: no broadcast movs
__device__ __forceinline__ void mm_accum(const u64* __restrict__ Xd,
                                         const float* __restrict__ Ws,
                                         int tr, int tc, u64 acc[8][4]) {
    const u64* xb = Xd + tr * 8 * XDS;
    const float* wb = Ws + 2 * tc;
#pragma unroll 4
    for (int k = 0; k < 128; k++) {
        u64 wv[4];
#pragma unroll
        for (int j = 0; j < 4; j++)
            wv[j] = *reinterpret_cast<const u64*>(wb + k * 128 + 32 * j);
#pragma unroll
        for (int i = 0; i < 8; i++) {
            u64 xd = xb[i * XDS + k];
#pragma unroll
            for (int j = 0; j < 4; j++)
                asm("fma.rn.f32x2 %0, %1, %2, %0;"
                    : "+l"(acc[i][j]) : "l"(wv[j]), "l"(xd));
        }
    }
}

#define SMEM_BYTES (128 * XDS * 8 + 128 * 128 * 4)

// ---------------- GEMM MODE 0: Y = X @ Wt ----------------
__global__ void __launch_bounds__(256, 1)
k_gemm0(const float* __restrict__ X, const float* __restrict__ Wt,
        float* __restrict__ out) {
    extern __shared__ char smraw[];
    u64* Xd = reinterpret_cast<u64*>(smraw);
    float* Ws = reinterpret_cast<float*>(smraw + 128 * XDS * 8);
    const int t = threadIdx.x;
    const size_t row0 = (size_t)blockIdx.x * 128;

    tile_load_dup(X + row0 * H, Xd, t);
    tile_load(Wt, Ws, t);
    __syncthreads();

    const int tc = t & 15, tr = t >> 4;
    u64 acc[8][4];
#pragma unroll
    for (int i = 0; i < 8; i++)
#pragma unroll
        for (int j = 0; j < 4; j++) acc[i][j] = 0ull;

    mm_accum(Xd, Ws, tr, tc, acc);

#pragma unroll
    for (int i = 0; i < 8; i++) {
        float* orow = out + (row0 + tr * 8 + i) * H + 2 * tc;
#pragma unroll
        for (int j = 0; j < 4; j++)
            *reinterpret_cast<u64*>(orow + 32 * j) = acc[i][j];
    }
}

// ---------------- Phase-1 E-side: self-GEMM + fused gather + LN ----------------
__global__ void __launch_bounds__(256, 1)
k_gemmE(const float* __restrict__ X, const float* __restrict__ Wt,
        const float* __restrict__ Y,
        const int* __restrict__ off, const int* __restrict__ lst,
        const float* __restrict__ ew,
        const float* __restrict__ bias, const float* __restrict__ gamma,
        const float* __restrict__ beta, float* __restrict__ out) {
    extern __shared__ char smraw[];
    u64* Xd = reinterpret_cast<u64*>(smraw);
    float* Ws = reinterpret_cast<float*>(smraw + 128 * XDS * 8);
    const int t = threadIdx.x;
    const size_t row0 = (size_t)blockIdx.x * 128;
    const int b = (int)(row0 / NE);
    const int e0 = (int)(row0 % NE);

    tile_load_dup(X + row0 * H, Xd, t);
    tile_load(Wt, Ws, t);
    __syncthreads();

    const int tc = t & 15, tr = t >> 4;
    u64 acc[8][4];
#pragma unroll
    for (int i = 0; i < 8; i++)
#pragma unroll
        for (int j = 0; j < 4; j++) acc[i][j] = 0ull;

    mm_accum(Xd, Ws, tr, tc, acc);

    float2 b2[4], g2[4], be2[4];
#pragma unroll
    for (int j = 0; j < 4; j++) {
        b2[j]  = *reinterpret_cast<const float2*>(bias  + 2 * tc + 32 * j);
        g2[j]  = *reinterpret_cast<const float2*>(gamma + 2 * tc + 32 * j);
        be2[j] = *reinterpret_cast<const float2*>(beta  + 2 * tc + 32 * j);
    }
    const float* Yb = Y + (size_t)b * ND * H + 2 * tc;

#pragma unroll
    for (int i = 0; i < 8; i++) {
        const int e = e0 + tr * 8 + i;
        const size_t r = row0 + tr * 8 + i;
        int s = off[e], en = off[e + 1];
        float sc = (1.0f / (1.0f + __expf(-ew[e]))) / fmaxf((float)(en - s), 1.0f);

        float2 ag[4];
#pragma unroll
        for (int j = 0; j < 4; j++) ag[j] = make_float2(0.f, 0.f);
        for (int p = s; p < en; ++p) {
            const float* yr = Yb + (size_t)lst[p] * H;
#pragma unroll
            for (int j = 0; j < 4; j++) {
                float2 v = *reinterpret_cast<const float2*>(yr + 32 * j);
                ag[j].x += v.x; ag[j].y += v.y;
            }
        }

        float tv[8];
        float ssum = 0.f, q = 0.f;
        const float* xrow = X + r * H + 2 * tc;
#pragma unroll
        for (int j = 0; j < 4; j++) {
            float plo, phi;
            asm("mov.b64 {%0, %1}, %2;" : "=f"(plo), "=f"(phi) : "l"(acc[i][j]));
            float2 x2 = *reinterpret_cast<const float2*>(xrow + 32 * j);
            float t0 = plo + ag[j].x * sc + b2[j].x; t0 = fmaxf(t0, 0.f); t0 += x2.x;
            float t1 = phi + ag[j].y * sc + b2[j].y; t1 = fmaxf(t1, 0.f); t1 += x2.y;
            tv[2 * j] = t0; tv[2 * j + 1] = t1;
            ssum += t0 + t1;
            q += t0 * t0 + t1 * t1;
        }
#pragma unroll
        for (int o = 8; o; o >>= 1) {
            ssum += __shfl_xor_sync(0xffffffffu, ssum, o, 16);
            q    += __shfl_xor_sync(0xffffffffu, q, o, 16);
        }
        float m = ssum * (1.0f / 128.0f);
        float rstd = rsqrtf(q * (1.0f / 128.0f) - m * m + 1e-5f);
        float* orow = out + r * H + 2 * tc;
#pragma unroll
        for (int j = 0; j < 4; j++) {
            float2 o2;
            o2.x = (tv[2 * j]     - m) * rstd * g2[j].x + be2[j].x;
            o2.y = (tv[2 * j + 1] - m) * rstd * g2[j].y + be2[j].y;
            *reinterpret_cast<float2*>(orow + 32 * j) = o2;
        }
    }
}

// ---------------- Phase-2 D-side dual GEMM + LN ----------------
__global__ void __launch_bounds__(256, 1)
k_gemmD(const float* __restrict__ X, const float* __restrict__ W1t,
        const float* __restrict__ A, const float* __restrict__ W2t,
        const float* __restrict__ bias, const float* __restrict__ gamma,
        const float* __restrict__ beta, float* __restrict__ out) {
    extern __shared__ char smraw[];
    u64* Xd = reinterpret_cast<u64*>(smraw);
    float* Ws = reinterpret_cast<float*>(smraw + 128 * XDS * 8);
    const int t = threadIdx.x;
    const size_t row0 = (size_t)blockIdx.x * 128;

    tile_load_dup(X + row0 * H, Xd, t);
    tile_load(W1t, Ws, t);
    __syncthreads();

    const int tc = t & 15, tr = t >> 4;
    u64 acc[8][4];
#pragma unroll
    for (int i = 0; i < 8; i++)
#pragma unroll
        for (int j = 0; j < 4; j++) acc[i][j] = 0ull;

    mm_accum(Xd, Ws, tr, tc, acc);
    __syncthreads();

    tile_load_dup(A + row0 * H, Xd, t);
    tile_load(W2t, Ws, t);
    __syncthreads();

    mm_accum(Xd, Ws, tr, tc, acc);

    float2 b2[4], g2[4], be2[4];
#pragma unroll
    for (int j = 0; j < 4; j++) {
        b2[j]  = *reinterpret_cast<const float2*>(bias  + 2 * tc + 32 * j);
        g2[j]  = *reinterpret_cast<const float2*>(gamma + 2 * tc + 32 * j);
        be2[j] = *reinterpret_cast<const float2*>(beta  + 2 * tc + 32 * j);
    }
#pragma unroll
    for (int i = 0; i < 8; i++) {
        const size_t r = row0 + tr * 8 + i;
        float tv[8];
        float ssum = 0.f, q = 0.f;
        const float* xrow = X + r * H + 2 * tc;
#pragma unroll
        for (int j = 0; j < 4; j++) {
            float plo, phi;
            asm("mov.b64 {%0, %1}, %2;" : "=f"(plo), "=f"(phi) : "l"(acc[i][j]));
            float2 x2 = *reinterpret_cast<const float2*>(xrow + 32 * j);
            float t0 = plo + b2[j].x; t0 = fmaxf(t0, 0.f); t0 += x2.x;
            float t1 = phi + b2[j].y; t1 = fmaxf(t1, 0.f); t1 += x2.y;
            tv[2 * j] = t0; tv[2 * j + 1] = t1;
            ssum += t0 + t1;
            q += t0 * t0 + t1 * t1;
        }
#pragma unroll
        for (int o = 8; o; o >>= 1) {
            ssum += __shfl_xor_sync(0xffffffffu, ssum, o, 16);
            q    += __shfl_xor_sync(0xffffffffu, q, o, 16);
        }
        float m = ssum * (1.0f / 128.0f);
        float rstd = rsqrtf(q * (1.0f / 128.0f) - m * m + 1e-5f);
        float* orow = out + r * H + 2 * tc;
#pragma unroll
        for (int j = 0; j < 4; j++) {
            float2 o2;
            o2.x = (tv[2 * j]     - m) * rstd * g2[j].x + be2[j].x;
            o2.y = (tv[2 * j + 1] - m) * rstd * g2[j].y + be2[j].y;
            *reinterpret_cast<float2*>(orow + 32 * j) = o2;
        }
    }
}

// ---------------- launch ----------------
extern "C" void kernel_launch(void* const* d_in, const int* in_sizes, int n_in,
                              void* d_out, int out_size) {
    const float* hD    = (const float*)d_in[0];
    const float* hE    = (const float*)d_in[1];
    const int*   e_d2e = (const int*)d_in[2];
    const int*   e_e2d = (const int*)d_in[3];
    const float* ew    = (const float*)d_in[4];
    const float* W_d2e    = (const float*)d_in[5];
    const float* W_e_self = (const float*)d_in[6];
    const float* b_e   = (const float*)d_in[7];
    const float* g_e   = (const float*)d_in[8];
    const float* be_e  = (const float*)d_in[9];
    const float* W_e2d    = (const float*)d_in[10];
    const float* W_d_self = (const float*)d_in[11];
    const float* b_d   = (const float*)d_in[12];
    const float* g_d   = (const float*)d_in[13];
    const float* be_d  = (const float*)d_in[14];

    float* out_hD = (float*)d_out;
    float* out_hE = (float*)d_out + (size_t)Bn * ND * H;

    float *pY, *pAggPre, *pWt;
    int *pOffE, *pLstE, *pOffD, *pLstD;
    cudaGetSymbolAddress((void**)&pY, g_Y);
    cudaGetSymbolAddress((void**)&pAggPre, g_aggPre);
    cudaGetSymbolAddress((void**)&pWt, g_Wt);
    cudaGetSymbolAddress((void**)&pOffE, g_offE);
    cudaGetSymbolAddress((void**)&pLstE, g_lstE);
    cudaGetSymbolAddress((void**)&pOffD, g_offD);
    cudaGetSymbolAddress((void**)&pLstD, g_lstD);

    float* Wt_d2e    = pWt + 0 * H * H;
    float* Wt_e_self = pWt + 1 * H * H;
    float* Wt_e2d    = pWt + 2 * H * H;
    float* Wt_d_self = pWt + 3 * H * H;

    const int smem = SMEM_BYTES;   // ~193 KB
    cudaFuncSetAttribute(k_gemm0, cudaFuncAttributeMaxDynamicSharedMemorySize, smem);
    cudaFuncSetAttribute(k_gemmE, cudaFuncAttributeMaxDynamicSharedMemorySize, smem);
    cudaFuncSetAttribute(k_gemmD, cudaFuncAttributeMaxDynamicSharedMemorySize, smem);

    // ---- setup: transposes + CSR ----
    k_wt4<<<256, 256>>>(W_d2e, W_e_self, W_e2d, W_d_self, pWt);
    k_zero<<<NE / 256, 256>>>();
    k_count<<<NEDGE / 256, 256>>>(e_d2e, e_e2d);
    k_scan2<<<2, 1024>>>();
    k_fill<<<NEDGE / 256, 256>>>(e_d2e, e_e2d);

    // ---- Phase 1: D -> E ----
    k_gemm0<<<(Bn * ND) / 128, 256, smem>>>(hD, Wt_d2e, pY);
    k_gemmE<<<(Bn * NE) / 128, 256, smem>>>(hE, Wt_e_self, pY, pOffE, pLstE, ew,
                                            b_e, g_e, be_e, out_hE);

    // ---- Phase 2: E -> D (commuted aggregation + dual GEMM) ----
    k_agg<<<(ND * Bn * 32) / 256, 256>>>(out_hE, pOffD, pLstD, pAggPre, ND, (long)NE * H);
    k_gemmD<<<(Bn * ND) / 128, 256, smem>>>(hD, Wt_d_self, pAggPre, Wt_e2d,
                                            b_d, g_d, be_d, out_hD);
}